// round 8
// baseline (speedup 1.0000x reference)
#include <cuda_runtime.h>
#include <math.h>
#include <stdint.h>

#define N 8192
#define D 1024
#define BM 128
#define BN 256
#define NTX (N / BN)         // 32 col tiles
#define NTY (N / BM)         // 64 row tiles
#define CHB 64               // bytes (=int8 elems) of K per chunk
#define NCHUNK (D / CHB)     // 16
#define ROWB 80              // padded smem row stride (64B data + 16B pad)
#define A_BYTES (BM * ROWB)            // 10240
#define STAGE_BYTES ((BM + BN) * ROWB) // 30720
#define DSMEM_BYTES (4 * STAGE_BYTES)  // 122880
#define QA 704.0f            // int8 quantization scale (clip at |x|=0.180 ~ 5.8 sigma)

// ---------------------------------------------------------------------------
// Device scratch
// ---------------------------------------------------------------------------
__device__ uint8_t g_A8[N * D];
__device__ uint8_t g_B8[N * D];
__device__ float4 g_rowP[NTX * N];   // (M, S, S2, -) per [tile][row]
__device__ float4 g_colP[NTY * N];
__device__ float g_diag[N];
__device__ double g_acc;

// ---------------------------------------------------------------------------
// Portable PTX helpers (sm_80 baseline -> OK under compute_103)
// ---------------------------------------------------------------------------
__device__ __forceinline__ uint32_t smem_u32(const void* p) {
    uint32_t a;
    asm("{ .reg .u64 t; cvta.to.shared.u64 t, %1; cvt.u32.u64 %0, t; }" : "=r"(a) : "l"(p));
    return a;
}

#define CP_ASYNC16(sa, gp) \
    asm volatile("cp.async.cg.shared.global [%0], [%1], 16;" :: "r"((uint32_t)(sa)), "l"(gp) : "memory")
#define CP_COMMIT() asm volatile("cp.async.commit_group;" ::: "memory")
#define CP_WAIT2()  asm volatile("cp.async.wait_group 2;" ::: "memory")

__device__ __forceinline__ void ldsm_x4(uint32_t* r, uint32_t addr) {
    asm volatile("ldmatrix.sync.aligned.m8n8.x4.shared.b16 {%0,%1,%2,%3}, [%4];"
                 : "=r"(r[0]), "=r"(r[1]), "=r"(r[2]), "=r"(r[3]) : "r"(addr));
}

// s8 IMMA: A frag 4 regs (16x32 s8), B frag 2 regs (32x8 s8), s32 accum.
__device__ __forceinline__ void mma_s8(int* d, const uint32_t* a, uint32_t b0, uint32_t b1) {
    asm volatile(
        "mma.sync.aligned.m16n8k32.row.col.s32.s8.s8.s32 "
        "{%0,%1,%2,%3}, {%4,%5,%6,%7}, {%8,%9}, {%0,%1,%2,%3};"
        : "+r"(d[0]), "+r"(d[1]), "+r"(d[2]), "+r"(d[3])
        : "r"(a[0]), "r"(a[1]), "r"(a[2]), "r"(a[3]), "r"(b0), "r"(b1));
}

__device__ __forceinline__ uint32_t quant4(float4 v) {
    int q0 = max(-127, min(127, __float2int_rn(v.x * QA)));
    int q1 = max(-127, min(127, __float2int_rn(v.y * QA)));
    int q2 = max(-127, min(127, __float2int_rn(v.z * QA)));
    int q3 = max(-127, min(127, __float2int_rn(v.w * QA)));
    return (uint32_t)(q0 & 0xff) | ((uint32_t)(q1 & 0xff) << 8) |
           ((uint32_t)(q2 & 0xff) << 16) | ((uint32_t)(q3 & 0xff) << 24);
}

// ---------------------------------------------------------------------------
__global__ void init_kernel() { g_acc = 0.0; }

// fp32 -> s8 (x QA) for both inputs, fused with exact fp32 diagonal dot.
__global__ void __launch_bounds__(256)
convert_diag_kernel(const float* __restrict__ A, const float* __restrict__ B,
                    const float* __restrict__ scale_p) {
    __shared__ float s_red[8];
    const int row = blockIdx.x;
    const int tid = threadIdx.x;
    const size_t base = (size_t)row * D + tid * 4;

    float4 a = *(const float4*)(A + base);
    float4 b = *(const float4*)(B + base);

    *(uint32_t*)(g_A8 + base) = quant4(a);
    *(uint32_t*)(g_B8 + base) = quant4(b);

    float s = a.x * b.x + a.y * b.y + a.z * b.z + a.w * b.w;
#pragma unroll
    for (int off = 16; off > 0; off >>= 1)
        s += __shfl_xor_sync(0xffffffffu, s, off);
    if ((tid & 31) == 0) s_red[tid >> 5] = s;
    __syncthreads();
    if (tid == 0) {
        float t = 0.0f;
#pragma unroll
        for (int w = 0; w < 8; w++) t += s_red[w];
        g_diag[row] = __ldg(scale_p) * t;
    }
}

// ---------------------------------------------------------------------------
// 128x256 tile s8 IMMA GEMM + fused LSE partials. Warp tile 64x64.
// ---------------------------------------------------------------------------
__device__ __forceinline__ void prefetch_chunk(const uint8_t* Ag, const uint8_t* Bg,
                                               uint32_t sbase, int tid, int c) {
    if (c < NCHUNK) {
        uint32_t st = sbase + (uint32_t)(c & 3) * STAGE_BYTES;
        int k0 = c * CHB;
#pragma unroll
        for (int j = 0; j < 6; j++) {
            int idx = tid + j * 256;          // 0..1535
            if (idx < 512) {
                int r = idx >> 2, g = idx & 3;
                CP_ASYNC16(st + r * ROWB + g * 16, Ag + (size_t)r * D + k0 + g * 16);
            } else {
                int e = idx - 512;            // 0..1023
                int r = e >> 2, g = e & 3;
                CP_ASYNC16(st + A_BYTES + r * ROWB + g * 16, Bg + (size_t)r * D + k0 + g * 16);
            }
        }
    }
    CP_COMMIT();
}

__global__ void __launch_bounds__(256, 1)
gemm_lse_mma(const float* __restrict__ scale_p) {
    extern __shared__ char dsm[];
    __shared__ float s_red[8];
    __shared__ float2 s_rows[4][128];
    __shared__ float2 s_cols[2][256];

    const int tid = threadIdx.x;
    const int wid = tid >> 5;
    const int lane = tid & 31;
    const int wm = wid & 1;    // M half  (rows wm*64 .. +64)
    const int wn = wid >> 1;   // N quarter (cols wn*64 .. +64)
    const int bx = blockIdx.x;
    const int by = blockIdx.y;

    const uint32_t sbase = smem_u32(dsm);
    const uint8_t* Ag = g_A8 + (size_t)by * BM * D;
    const uint8_t* Bg = g_B8 + (size_t)bx * BN * D;

    int iacc[4][8][4];
#pragma unroll
    for (int mt = 0; mt < 4; mt++)
#pragma unroll
        for (int nt = 0; nt < 8; nt++)
#pragma unroll
            for (int i = 0; i < 4; i++) iacc[mt][nt][i] = 0;

    const uint32_t lOff = (uint32_t)((lane & 15) * ROWB + (lane >> 4) * 16);
    const uint32_t aOff = sbase + lOff + (uint32_t)(wm * 64 * ROWB);
    const uint32_t bOff = sbase + A_BYTES + lOff + (uint32_t)(wn * 64 * ROWB);

    prefetch_chunk(Ag, Bg, sbase, tid, 0);
    prefetch_chunk(Ag, Bg, sbase, tid, 1);
    prefetch_chunk(Ag, Bg, sbase, tid, 2);

    for (int c = 0; c < NCHUNK; c++) {
        CP_WAIT2();            // chunk c resident
        __syncthreads();       // all warps done reading stage (c-1)&3
        prefetch_chunk(Ag, Bg, sbase, tid, c + 3);

        const uint32_t stoff = (uint32_t)(c & 3) * STAGE_BYTES;
#pragma unroll
        for (int ks = 0; ks < 2; ks++) {   // two k32 steps (32B each)
            uint32_t afr[4][4];
#pragma unroll
            for (int mt = 0; mt < 4; mt++)
                ldsm_x4(afr[mt], aOff + stoff + (uint32_t)(mt * 16 * ROWB + ks * 32));
            uint32_t bfr[4][4];
#pragma unroll
            for (int q = 0; q < 4; q++)
                ldsm_x4(bfr[q], bOff + stoff + (uint32_t)(q * 16 * ROWB + ks * 32));
#pragma unroll
            for (int mt = 0; mt < 4; mt++)
#pragma unroll
                for (int nt = 0; nt < 8; nt++)
                    mma_s8(iacc[mt][nt], afr[mt],
                           bfr[nt >> 1][nt & 1], bfr[nt >> 1][(nt & 1) + 2]);
        }
    }

    // ---- Fused epilogue: logits = iacc * scale / QA^2 ----
    const float scale = __ldg(scale_p) / (QA * QA);
    float acc[4][8][4];
#pragma unroll
    for (int mt = 0; mt < 4; mt++)
#pragma unroll
        for (int nt = 0; nt < 8; nt++)
#pragma unroll
            for (int i = 0; i < 4; i++) acc[mt][nt][i] = (float)iacc[mt][nt][i] * scale;

    float m = -INFINITY;
#pragma unroll
    for (int mt = 0; mt < 4; mt++)
#pragma unroll
        for (int nt = 0; nt < 8; nt++)
#pragma unroll
            for (int i = 0; i < 4; i++) m = fmaxf(m, acc[mt][nt][i]);
#pragma unroll
    for (int off = 16; off > 0; off >>= 1)
        m = fmaxf(m, __shfl_xor_sync(0xffffffffu, m, off));
    if (lane == 0) s_red[wid] = m;
    __syncthreads();
    float Mt = s_red[0];
#pragma unroll
    for (int w = 1; w < 8; w++) Mt = fmaxf(Mt, s_red[w]);

#pragma unroll
    for (int mt = 0; mt < 4; mt++)
#pragma unroll
        for (int nt = 0; nt < 8; nt++)
#pragma unroll
            for (int i = 0; i < 4; i++)
                acc[mt][nt][i] = __expf(acc[mt][nt][i] - Mt);

    // Row partial sums (S and S2). Accum layout: reg i: row (i>>1)*8+(lane>>2),
    // col (lane&3)*2+(i&1), within each 16x8 sub-tile.
#pragma unroll
    for (int mt = 0; mt < 4; mt++)
#pragma unroll
        for (int half = 0; half < 2; half++) {
            float rs = 0.0f, r2 = 0.0f;
#pragma unroll
            for (int nt = 0; nt < 8; nt++) {
                float v0 = acc[mt][nt][half * 2], v1 = acc[mt][nt][half * 2 + 1];
                rs += v0 + v1;
                r2 += v0 * v0 + v1 * v1;
            }
            rs += __shfl_xor_sync(0xffffffffu, rs, 1);
            r2 += __shfl_xor_sync(0xffffffffu, r2, 1);
            rs += __shfl_xor_sync(0xffffffffu, rs, 2);
            r2 += __shfl_xor_sync(0xffffffffu, r2, 2);
            if ((lane & 3) == 0)
                s_rows[wn][wm * 64 + mt * 16 + half * 8 + (lane >> 2)] = make_float2(rs, r2);
        }

    // Col partial sums
#pragma unroll
    for (int nt = 0; nt < 8; nt++)
#pragma unroll
        for (int cc = 0; cc < 2; cc++) {
            float cs = 0.0f, c2 = 0.0f;
#pragma unroll
            for (int mt = 0; mt < 4; mt++) {
                float v0 = acc[mt][nt][cc], v1 = acc[mt][nt][cc + 2];
                cs += v0 + v1;
                c2 += v0 * v0 + v1 * v1;
            }
            cs += __shfl_xor_sync(0xffffffffu, cs, 4);
            c2 += __shfl_xor_sync(0xffffffffu, c2, 4);
            cs += __shfl_xor_sync(0xffffffffu, cs, 8);
            c2 += __shfl_xor_sync(0xffffffffu, c2, 8);
            cs += __shfl_xor_sync(0xffffffffu, cs, 16);
            c2 += __shfl_xor_sync(0xffffffffu, c2, 16);
            if (lane < 4)
                s_cols[wm][wn * 64 + nt * 8 + (lane & 3) * 2 + cc] = make_float2(cs, c2);
        }
    __syncthreads();

    if (tid < 128) {
        float rs = s_rows[0][tid].x + s_rows[1][tid].x + s_rows[2][tid].x + s_rows[3][tid].x;
        float r2 = s_rows[0][tid].y + s_rows[1][tid].y + s_rows[2][tid].y + s_rows[3][tid].y;
        g_rowP[(size_t)bx * N + by * BM + tid] = make_float4(Mt, rs, r2, 0.0f);
    }
    {
        float cs = s_cols[0][tid].x + s_cols[1][tid].x;
        float c2 = s_cols[0][tid].y + s_cols[1][tid].y;
        g_colP[(size_t)by * N + bx * BN + tid] = make_float4(Mt, cs, c2, 0.0f);
    }
}

// ---------------------------------------------------------------------------
// Combine partials -> bias-corrected lse per row/col, subtract diag, reduce.
// Blocks 0..31: rows. Blocks 32..63: cols.
// ---------------------------------------------------------------------------
__global__ void reduce_kernel(const float* __restrict__ scale_p) {
    const bool rowdir = blockIdx.x < 32;
    const int i = (rowdir ? blockIdx.x : blockIdx.x - 32) * 256 + threadIdx.x;
    const int nt = rowdir ? NTX : NTY;
    const float4* P = rowdir ? g_rowP : g_colP;

    float m = -INFINITY, s = 0.0f, s2 = 0.0f;
    for (int t = 0; t < nt; t++) {
        float4 p = P[(size_t)t * N + i];
        float nm = fmaxf(m, p.x);
        float e1 = __expf(m - nm), e2 = __expf(p.x - nm);
        s  = s  * e1      + p.y * e2;
        s2 = s2 * e1 * e1 + p.z * e2 * e2;
        m = nm;
    }
    // convexity bias correction: E[lse(x+d)] - lse(x) ~= 0.5*sig2*(1 - sum p^2)
    // sig2 = s^2 * 2 * sigma_q^2, sigma_q = 1/(QA*sqrt(12))  ->  s^2/(6*QA^2)
    float sc = __ldg(scale_p);
    float sig2 = sc * sc / (6.0f * QA * QA);
    float sump2 = s2 / (s * s);
    float lse = m + logf(s) - 0.5f * sig2 * (1.0f - sump2);

    float v = lse - g_diag[i];

    __shared__ float sm[256];
    sm[threadIdx.x] = v;
    __syncthreads();
    for (int off = 128; off > 0; off >>= 1) {
        if (threadIdx.x < off) sm[threadIdx.x] += sm[threadIdx.x + off];
        __syncthreads();
    }
    if (threadIdx.x == 0) atomicAdd(&g_acc, (double)sm[0]);
}

__global__ void final_kernel(float* out) {
    out[0] = (float)(g_acc / (2.0 * (double)N));
}

// ---------------------------------------------------------------------------
extern "C" void kernel_launch(void* const* d_in, const int* in_sizes, int n_in,
                              void* d_out, int out_size) {
    const float* img   = (const float*)d_in[0];
    const float* txt   = (const float*)d_in[1];
    const float* scale = (const float*)d_in[2];
    float* out = (float*)d_out;

    cudaFuncSetAttribute(gemm_lse_mma, cudaFuncAttributeMaxDynamicSharedMemorySize, DSMEM_BYTES);

    init_kernel<<<1, 1>>>();
    convert_diag_kernel<<<N, 256>>>(img, txt, scale);

    dim3 grid(NTX, NTY);  // 32 x 64
    gemm_lse_mma<<<grid, 256, DSMEM_BYTES>>>(scale);

    reduce_kernel<<<64, 256>>>(scale);
    final_kernel<<<1, 1>>>(out);
}

// round 9
// speedup vs baseline: 2.2079x; 2.2079x over previous
#include <cuda_runtime.h>
#include <math.h>
#include <stdint.h>

#define N 8192
#define D 1024
#define BM 128
#define BN 256
#define NTX (N / BN)         // 32 col tiles
#define NTY (N / BM)         // 64 row tiles
#define CHB 64               // bytes (=fp8 elems) of K per chunk
#define NCHUNK (D / CHB)     // 16
#define ROWB 80              // padded smem row stride (64B data + 16B pad)
#define A_BYTES (BM * ROWB)            // 10240
#define STAGE_BYTES ((BM + BN) * ROWB) // 30720
#define DSMEM_BYTES (4 * STAGE_BYTES)  // 122880
#define QSCALE 64.0f         // input quantization scale (per operand)

// ---------------------------------------------------------------------------
// Device scratch
// ---------------------------------------------------------------------------
__device__ uint8_t g_A8[N * D];
__device__ uint8_t g_B8[N * D];
__device__ float2 g_rowP[NTX * N];   // (M, S) per [tile][row]
__device__ float2 g_colP[NTY * N];
__device__ float g_diag[N];    // exact fp32 logit (r,r)
__device__ float g_offx[N];    // exact fp32 logit (r,r^1)
__device__ float g_diag8[N];   // fp8-path logit (r,r)
__device__ float g_off8[N];    // fp8-path logit (r,r^1)
__device__ float g_corr;       // measured lse bias
__device__ double g_acc;

// ---------------------------------------------------------------------------
// Portable PTX helpers (sm_80/sm_89 baseline -> OK under compute_103)
// ---------------------------------------------------------------------------
__device__ __forceinline__ uint32_t smem_u32(const void* p) {
    uint32_t a;
    asm("{ .reg .u64 t; cvta.to.shared.u64 t, %1; cvt.u32.u64 %0, t; }" : "=r"(a) : "l"(p));
    return a;
}

#define CP_ASYNC16(sa, gp) \
    asm volatile("cp.async.cg.shared.global [%0], [%1], 16;" :: "r"((uint32_t)(sa)), "l"(gp) : "memory")
#define CP_COMMIT() asm volatile("cp.async.commit_group;" ::: "memory")
#define CP_WAIT2()  asm volatile("cp.async.wait_group 2;" ::: "memory")

__device__ __forceinline__ void ldsm_x4(uint32_t* r, uint32_t addr) {
    asm volatile("ldmatrix.sync.aligned.m8n8.x4.shared.b16 {%0,%1,%2,%3}, [%4];"
                 : "=r"(r[0]), "=r"(r[1]), "=r"(r[2]), "=r"(r[3]) : "r"(addr));
}

// e4m3 mma: A frag 4 regs (16x32 fp8), B frag 2 regs (32x8 fp8), fp32 accum.
__device__ __forceinline__ void mma_fp8(float* d, const uint32_t* a, uint32_t b0, uint32_t b1) {
    asm volatile(
        "mma.sync.aligned.m16n8k32.row.col.f32.e4m3.e4m3.f32 "
        "{%0,%1,%2,%3}, {%4,%5,%6,%7}, {%8,%9}, {%0,%1,%2,%3};"
        : "+f"(d[0]), "+f"(d[1]), "+f"(d[2]), "+f"(d[3])
        : "r"(a[0]), "r"(a[1]), "r"(a[2]), "r"(a[3]), "r"(b0), "r"(b1));
}

__device__ __forceinline__ uint16_t cvt_e4m3x2(float hi, float lo) {
    uint16_t p;
    asm("cvt.rn.satfinite.e4m3x2.f32 %0, %1, %2;" : "=h"(p) : "f"(hi), "f"(lo));
    return p;
}

// ---------------------------------------------------------------------------
__global__ void init_kernel() { g_acc = 0.0; }

// fp32 -> e4m3 (x QSCALE) for both inputs, fused with exact fp32 dots for
// the calibration pairs (row,row) and (row,row^1).
__global__ void __launch_bounds__(256)
convert_diag_kernel(const float* __restrict__ A, const float* __restrict__ B,
                    const float* __restrict__ scale_p) {
    __shared__ float s_red[8], s_red2[8];
    const int row = blockIdx.x;
    const int tid = threadIdx.x;
    const size_t base = (size_t)row * D + tid * 4;
    const size_t pbase = (size_t)(row ^ 1) * D + tid * 4;

    float4 a = *(const float4*)(A + base);
    float4 b = *(const float4*)(B + base);
    float4 bp = *(const float4*)(B + pbase);

    uint32_t wa = (uint32_t)cvt_e4m3x2(a.y * QSCALE, a.x * QSCALE)
                | ((uint32_t)cvt_e4m3x2(a.w * QSCALE, a.z * QSCALE) << 16);
    uint32_t wb = (uint32_t)cvt_e4m3x2(b.y * QSCALE, b.x * QSCALE)
                | ((uint32_t)cvt_e4m3x2(b.w * QSCALE, b.z * QSCALE) << 16);
    *(uint32_t*)(g_A8 + base) = wa;
    *(uint32_t*)(g_B8 + base) = wb;

    float s  = a.x * b.x  + a.y * b.y  + a.z * b.z  + a.w * b.w;
    float s2 = a.x * bp.x + a.y * bp.y + a.z * bp.z + a.w * bp.w;
#pragma unroll
    for (int off = 16; off > 0; off >>= 1) {
        s  += __shfl_xor_sync(0xffffffffu, s, off);
        s2 += __shfl_xor_sync(0xffffffffu, s2, off);
    }
    if ((tid & 31) == 0) { s_red[tid >> 5] = s; s_red2[tid >> 5] = s2; }
    __syncthreads();
    if (tid == 0) {
        float t = 0.0f, t2 = 0.0f;
#pragma unroll
        for (int w = 0; w < 8; w++) { t += s_red[w]; t2 += s_red2[w]; }
        float sc = __ldg(scale_p);
        g_diag[row] = sc * t;
        g_offx[row] = sc * t2;
    }
}

// ---------------------------------------------------------------------------
// 128x256 tile e4m3 mma.sync GEMM + fused LSE partials. Warp tile 64x64.
// ---------------------------------------------------------------------------
__device__ __forceinline__ void prefetch_chunk(const uint8_t* Ag, const uint8_t* Bg,
                                               uint32_t sbase, int tid, int c) {
    if (c < NCHUNK) {
        uint32_t st = sbase + (uint32_t)(c & 3) * STAGE_BYTES;
        int k0 = c * CHB;
#pragma unroll
        for (int j = 0; j < 6; j++) {
            int idx = tid + j * 256;          // 0..1535
            if (idx < 512) {
                int r = idx >> 2, g = idx & 3;
                CP_ASYNC16(st + r * ROWB + g * 16, Ag + (size_t)r * D + k0 + g * 16);
            } else {
                int e = idx - 512;            // 0..1023
                int r = e >> 2, g = e & 3;
                CP_ASYNC16(st + A_BYTES + r * ROWB + g * 16, Bg + (size_t)r * D + k0 + g * 16);
            }
        }
    }
    CP_COMMIT();
}

__global__ void __launch_bounds__(256, 1)
gemm_lse_mma(const float* __restrict__ scale_p) {
    extern __shared__ char dsm[];
    __shared__ float s_red[8];
    __shared__ float s_rows[4][128];
    __shared__ float s_cols[2][256];

    const int tid = threadIdx.x;
    const int wid = tid >> 5;
    const int lane = tid & 31;
    const int wm = wid & 1;    // M half  (rows wm*64 .. +64)
    const int wn = wid >> 1;   // N quarter (cols wn*64 .. +64)
    const int bx = blockIdx.x;
    const int by = blockIdx.y;

    const uint32_t sbase = smem_u32(dsm);
    const uint8_t* Ag = g_A8 + (size_t)by * BM * D;
    const uint8_t* Bg = g_B8 + (size_t)bx * BN * D;

    float acc[4][8][4];
#pragma unroll
    for (int mt = 0; mt < 4; mt++)
#pragma unroll
        for (int nt = 0; nt < 8; nt++)
#pragma unroll
            for (int i = 0; i < 4; i++) acc[mt][nt][i] = 0.0f;

    const uint32_t lOff = (uint32_t)((lane & 15) * ROWB + (lane >> 4) * 16);
    const uint32_t aOff = sbase + lOff + (uint32_t)(wm * 64 * ROWB);
    const uint32_t bOff = sbase + A_BYTES + lOff + (uint32_t)(wn * 64 * ROWB);

    prefetch_chunk(Ag, Bg, sbase, tid, 0);
    prefetch_chunk(Ag, Bg, sbase, tid, 1);
    prefetch_chunk(Ag, Bg, sbase, tid, 2);

    for (int c = 0; c < NCHUNK; c++) {
        CP_WAIT2();            // chunk c resident
        __syncthreads();       // all warps done reading stage (c-1)&3
        prefetch_chunk(Ag, Bg, sbase, tid, c + 3);

        const uint32_t stoff = (uint32_t)(c & 3) * STAGE_BYTES;
#pragma unroll
        for (int ks = 0; ks < 2; ks++) {   // two k32 steps (32B each)
            uint32_t afr[4][4];
#pragma unroll
            for (int mt = 0; mt < 4; mt++)
                ldsm_x4(afr[mt], aOff + stoff + (uint32_t)(mt * 16 * ROWB + ks * 32));
            uint32_t bfr[4][4];
#pragma unroll
            for (int q = 0; q < 4; q++)
                ldsm_x4(bfr[q], bOff + stoff + (uint32_t)(q * 16 * ROWB + ks * 32));
#pragma unroll
            for (int mt = 0; mt < 4; mt++)
#pragma unroll
                for (int nt = 0; nt < 8; nt++)
                    mma_fp8(acc[mt][nt], afr[mt],
                            bfr[nt >> 1][nt & 1], bfr[nt >> 1][(nt & 1) + 2]);
        }
    }

    // ---- Fused epilogue: logits = acc * scale / QSCALE^2 ----
    const float scale = __ldg(scale_p) / (QSCALE * QSCALE);
#pragma unroll
    for (int mt = 0; mt < 4; mt++)
#pragma unroll
        for (int nt = 0; nt < 8; nt++)
#pragma unroll
            for (int i = 0; i < 4; i++) acc[mt][nt][i] *= scale;

    // Calibration extraction: this CTA holds global (r,r) and (r,r^1) logits
    // iff bx == by>>1. Local diag: c_loc == r_loc + 128*(by&1).
    if (bx == (by >> 1)) {
        const int cbase = (by & 1) << 7;
#pragma unroll
        for (int mt = 0; mt < 4; mt++)
#pragma unroll
            for (int nt = 0; nt < 8; nt++)
#pragma unroll
                for (int i = 0; i < 4; i++) {
                    int r_loc = wm * 64 + mt * 16 + ((i >> 1) << 3) + (lane >> 2);
                    int c_loc = wn * 64 + nt * 8 + ((lane & 3) << 1) + (i & 1);
                    if (c_loc == r_loc + cbase)
                        g_diag8[by * BM + r_loc] = acc[mt][nt][i];
                    if (c_loc == (r_loc ^ 1) + cbase)
                        g_off8[by * BM + r_loc] = acc[mt][nt][i];
                }
    }

    float m = -INFINITY;
#pragma unroll
    for (int mt = 0; mt < 4; mt++)
#pragma unroll
        for (int nt = 0; nt < 8; nt++)
#pragma unroll
            for (int i = 0; i < 4; i++) m = fmaxf(m, acc[mt][nt][i]);
#pragma unroll
    for (int off = 16; off > 0; off >>= 1)
        m = fmaxf(m, __shfl_xor_sync(0xffffffffu, m, off));
    if (lane == 0) s_red[wid] = m;
    __syncthreads();
    float Mt = s_red[0];
#pragma unroll
    for (int w = 1; w < 8; w++) Mt = fmaxf(Mt, s_red[w]);

#pragma unroll
    for (int mt = 0; mt < 4; mt++)
#pragma unroll
        for (int nt = 0; nt < 8; nt++)
#pragma unroll
            for (int i = 0; i < 4; i++)
                acc[mt][nt][i] = __expf(acc[mt][nt][i] - Mt);

    // Row partial sums. Accum layout: reg i: row (i>>1)*8+(lane>>2),
    // col (lane&3)*2+(i&1), within each 16x8 sub-tile.
#pragma unroll
    for (int mt = 0; mt < 4; mt++)
#pragma unroll
        for (int half = 0; half < 2; half++) {
            float rs = 0.0f;
#pragma unroll
            for (int nt = 0; nt < 8; nt++)
                rs += acc[mt][nt][half * 2] + acc[mt][nt][half * 2 + 1];
            rs += __shfl_xor_sync(0xffffffffu, rs, 1);
            rs += __shfl_xor_sync(0xffffffffu, rs, 2);
            if ((lane & 3) == 0)
                s_rows[wn][wm * 64 + mt * 16 + half * 8 + (lane >> 2)] = rs;
        }

    // Col partial sums
#pragma unroll
    for (int nt = 0; nt < 8; nt++)
#pragma unroll
        for (int cc = 0; cc < 2; cc++) {
            float cs = 0.0f;
#pragma unroll
            for (int mt = 0; mt < 4; mt++)
                cs += acc[mt][nt][cc] + acc[mt][nt][cc + 2];
            cs += __shfl_xor_sync(0xffffffffu, cs, 4);
            cs += __shfl_xor_sync(0xffffffffu, cs, 8);
            cs += __shfl_xor_sync(0xffffffffu, cs, 16);
            if (lane < 4)
                s_cols[wm][wn * 64 + nt * 8 + (lane & 3) * 2 + cc] = cs;
        }
    __syncthreads();

    if (tid < 128) {
        float rs = s_rows[0][tid] + s_rows[1][tid] + s_rows[2][tid] + s_rows[3][tid];
        g_rowP[(size_t)bx * N + by * BM + tid] = make_float2(Mt, rs);
    }
    {
        float cs = s_cols[0][tid] + s_cols[1][tid];
        g_colP[(size_t)by * N + bx * BN + tid] = make_float2(Mt, cs);
    }
}

// ---------------------------------------------------------------------------
// Measure fp8 logit noise on the 2N calibration pairs -> lse bias correction.
// corr = log E[exp(delta)] ~= log1p(E[d] + E[d^2]/2)
// ---------------------------------------------------------------------------
__global__ void __launch_bounds__(256)
stats_kernel() {
    __shared__ float sm[8], sm2[8];
    const int tid = threadIdx.x;
    float s = 0.0f, s2 = 0.0f;
    for (int k = tid; k < N; k += 256) {
        float d1 = g_diag8[k] - g_diag[k];
        float d2 = g_off8[k] - g_offx[k];
        s += d1 + d2;
        s2 += d1 * d1 + d2 * d2;
    }
#pragma unroll
    for (int off = 16; off > 0; off >>= 1) {
        s  += __shfl_xor_sync(0xffffffffu, s, off);
        s2 += __shfl_xor_sync(0xffffffffu, s2, off);
    }
    if ((tid & 31) == 0) { sm[tid >> 5] = s; sm2[tid >> 5] = s2; }
    __syncthreads();
    if (tid == 0) {
        float ts = 0.0f, t2 = 0.0f;
#pragma unroll
        for (int w = 0; w < 8; w++) { ts += sm[w]; t2 += sm2[w]; }
        float mean = ts / (2.0f * N);
        float m2   = t2 / (2.0f * N);
        g_corr = log1pf(mean + 0.5f * m2);
    }
}

// ---------------------------------------------------------------------------
// Combine partials -> bias-corrected lse per row/col, subtract diag, reduce.
// Blocks 0..31: rows (NTX tiles). Blocks 32..63: cols (NTY tiles).
// ---------------------------------------------------------------------------
__global__ void reduce_kernel() {
    const bool rowdir = blockIdx.x < 32;
    const int i = (rowdir ? blockIdx.x : blockIdx.x - 32) * 256 + threadIdx.x;
    const int nt = rowdir ? NTX : NTY;
    const float2* P = rowdir ? g_rowP : g_colP;

    float m = -INFINITY, s = 0.0f;
    for (int t = 0; t < nt; t++) {
        float2 p = P[(size_t)t * N + i];
        float nm = fmaxf(m, p.x);
        s = s * __expf(m - nm) + p.y * __expf(p.x - nm);
        m = nm;
    }
    float lse = m + logf(s) - g_corr;
    float v = lse - g_diag[i];

    __shared__ float sm[256];
    sm[threadIdx.x] = v;
    __syncthreads();
    for (int off = 128; off > 0; off >>= 1) {
        if (threadIdx.x < off) sm[threadIdx.x] += sm[threadIdx.x + off];
        __syncthreads();
    }
    if (threadIdx.x == 0) atomicAdd(&g_acc, (double)sm[0]);
}

__global__ void final_kernel(float* out) {
    out[0] = (float)(g_acc / (2.0 * (double)N));
}

// ---------------------------------------------------------------------------
extern "C" void kernel_launch(void* const* d_in, const int* in_sizes, int n_in,
                              void* d_out, int out_size) {
    const float* img   = (const float*)d_in[0];
    const float* txt   = (const float*)d_in[1];
    const float* scale = (const float*)d_in[2];
    float* out = (float*)d_out;

    cudaFuncSetAttribute(gemm_lse_mma, cudaFuncAttributeMaxDynamicSharedMemorySize, DSMEM_BYTES);

    init_kernel<<<1, 1>>>();
    convert_diag_kernel<<<N, 256>>>(img, txt, scale);

    dim3 grid(NTX, NTY);  // 32 x 64
    gemm_lse_mma<<<grid, 256, DSMEM_BYTES>>>(scale);

    stats_kernel<<<1, 256>>>();
    reduce_kernel<<<64, 256>>>();
    final_kernel<<<1, 1>>>(out);
}